// round 1
// baseline (speedup 1.0000x reference)
#include <cuda_runtime.h>
#include <cstdint>

// FilterAugment: out[b,f,t] = x[b,f,t] * 10^(gain_db(b,f)/20)
// B=64, F=256, T=2048 (fp32). Pure HBM-bound stream: 268 MB total traffic.
//
// One CTA per (b,f) row. All threads compute the scalar gain redundantly
// (tiny ALU cost), then stream T=2048 floats as float4 (2 iters of 256 thr).

#define F_DIM 256
#define T_DIM 2048
#define NBP1  5           // N_BAND + 1 boundaries
// log2(10)/20
#define DB_TO_LOG2 0.166096404744368f

__global__ __launch_bounds__(256, 8)
void filter_augment_kernel(const float* __restrict__ x,
                           const float* __restrict__ band_factors,
                           const int*   __restrict__ bndry,
                           float* __restrict__ out)
{
    const int bfi = blockIdx.x;          // b*F + f
    const int f   = bfi & (F_DIM - 1);
    const int b   = bfi >> 8;            // F=256 -> shift 8

    // searchsorted(bndry, f, 'right') - 1, clipped to [0, NBP1-2]
    // bndry[0]==0 so count>=1; idx = sum_{j=1..4}(f >= bndry[j]), clip to 3.
    int idx = 0;
    #pragma unroll
    for (int j = 1; j < NBP1; ++j)
        idx += (f >= __ldg(&bndry[j])) ? 1 : 0;
    if (idx > NBP1 - 2) idx = NBP1 - 2;

    const int lo    = __ldg(&bndry[idx]);
    const int width = __ldg(&bndry[idx + 1]) - lo;
    const float denom = (float)max(width - 1, 1);
    const float t = (float)(f - lo) / denom;

    const float g0 = __ldg(&band_factors[b * NBP1 + idx]);
    const float g1 = __ldg(&band_factors[b * NBP1 + idx + 1]);
    const float gain_db = fmaf(g1 - g0, t, g0);
    const float filt = exp2f(gain_db * DB_TO_LOG2);

    // Stream the row: T=2048 floats = 512 float4, 256 threads x 2 iters.
    const size_t base = (size_t)bfi * T_DIM;
    const float4* __restrict__ in4  = reinterpret_cast<const float4*>(x + base);
    float4* __restrict__       out4 = reinterpret_cast<float4*>(out + base);

    const int tid = threadIdx.x;
    #pragma unroll
    for (int i = 0; i < 2; ++i) {
        const int k = tid + i * 256;     // 0..511
        float4 v = in4[k];
        v.x *= filt; v.y *= filt; v.z *= filt; v.w *= filt;
        out4[k] = v;
    }
}

extern "C" void kernel_launch(void* const* d_in, const int* in_sizes, int n_in,
                              void* d_out, int out_size)
{
    const float* features     = (const float*)d_in[0];
    const float* band_factors = (const float*)d_in[1];
    const int*   bndry        = (const int*)d_in[2];
    float* out = (float*)d_out;

    // B*F rows; B derived from band_factors size (B * (N_BAND+1))
    const int B = in_sizes[1] / NBP1;
    const int nrows = B * F_DIM;

    filter_augment_kernel<<<nrows, 256>>>(features, band_factors, bndry, out);
}